// round 1
// baseline (speedup 1.0000x reference)
#include <cuda_runtime.h>

#define NMAX  1536
#define SORTN 2048
#define TPB   512
#define NITER 20

__device__ int g_offsets[2049];
__device__ int g_maxdeg;

// ---------------------------------------------------------------------------
// Kernel 1: exclusive-scan of sizes -> g_offsets, reset g_maxdeg.
// One block, 1024 threads, each handles 2 elements (B <= 2048).
// ---------------------------------------------------------------------------
__global__ void scan_offsets_kernel(const int* __restrict__ sizes, int B) {
    __shared__ int warp_sums[32];
    int t = threadIdx.x;
    if (t == 0) g_maxdeg = 0;

    int i0 = 2 * t, i1 = 2 * t + 1;
    int s0 = (i0 < B) ? sizes[i0] : 0;
    int s1 = (i1 < B) ? sizes[i1] : 0;
    int tot = s0 + s1;

    int lane = t & 31, wid = t >> 5;
    int v = tot;
#pragma unroll
    for (int d = 1; d < 32; d <<= 1) {
        int o = __shfl_up_sync(0xffffffffu, v, d);
        if (lane >= d) v += o;
    }
    if (lane == 31) warp_sums[wid] = v;
    __syncthreads();
    if (wid == 0) {
        int w = warp_sums[lane];
#pragma unroll
        for (int d = 1; d < 32; d <<= 1) {
            int o = __shfl_up_sync(0xffffffffu, w, d);
            if (lane >= d) w += o;
        }
        warp_sums[lane] = w;
    }
    __syncthreads();
    int warp_excl = (wid > 0) ? warp_sums[wid - 1] : 0;
    int incl = v + warp_excl;   // inclusive prefix over pair totals
    int excl = incl - tot;      // exclusive start of this pair
    if (i0 < B) g_offsets[i0] = excl;
    if (i1 < B) g_offsets[i1] = excl + s0;
    if (i1 == B - 1) g_offsets[B] = incl;
}

// ---------------------------------------------------------------------------
// Kernel 2: per-group degree counts (chain degree analytic + random edges),
// global max via atomicMax.
// ---------------------------------------------------------------------------
__global__ void deg_kernel(const int* __restrict__ sizes,
                           const int* __restrict__ edges,
                           int N, int B) {
    __shared__ int cnt[NMAX];
    __shared__ int red[8];
    int g = blockIdx.x;
    int n = sizes[g];
    int off = g_offsets[g];
    int t = threadIdx.x;

    for (int i = t; i < n; i += blockDim.x)
        cnt[i] = (n == 1) ? 0 : ((i == 0 || i == n - 1) ? 1 : 2);
    __syncthreads();

    int reBase = (N - B) + off;  // random-edge region for this group
    for (int i = t; i < n; i += blockDim.x) {
        int a = edges[2 * (reBase + i)]     - off;
        int b = edges[2 * (reBase + i) + 1] - off;
        atomicAdd(&cnt[a], 1);
        atomicAdd(&cnt[b], 1);
    }
    __syncthreads();

    int m = 0;
    for (int i = t; i < n; i += blockDim.x) m = max(m, cnt[i]);
#pragma unroll
    for (int d = 16; d; d >>= 1) m = max(m, __shfl_xor_sync(0xffffffffu, m, d));
    int lane = t & 31, wid = t >> 5;
    if (lane == 0) red[wid] = m;
    __syncthreads();
    if (t == 0) {
        int nw = (blockDim.x + 31) / 32;
        int mm = red[0];
        for (int w = 1; w < nw; ++w) mm = max(mm, red[w]);
        atomicMax(&g_maxdeg, mm);
    }
}

// ---------------------------------------------------------------------------
// Kernel 3: fused per-group solve. One block per group.
// Phase 1 (iterations) smem layout (floats):
//   xs[0..1536) ys[1536..3072) uc[3072..4608) ur[4608..6144) eab[6144..7680)
// Phase 2 (sparsemax) reuses dead regions:
//   S  = sm+3072 (2048 floats, sorted z)   overlaps uc + ur[:512]
//   CS = sm+5120 (2048 floats, cumsum)     overlaps ur[512:] + eab
// ---------------------------------------------------------------------------
__global__ void __launch_bounds__(TPB)
main_kernel(const float* __restrict__ x,
            const int*   __restrict__ sizes,
            const int*   __restrict__ edges,
            float*       __restrict__ out,
            int N, int B) {
    extern __shared__ float sm[];
    float*    xs  = sm;
    float*    ys  = sm + NMAX;
    float*    uc  = sm + 2 * NMAX;
    float*    ur  = sm + 3 * NMAX;
    unsigned* eab = (unsigned*)(sm + 4 * NMAX);
    float*    S   = sm + 2 * NMAX;
    float*    CS  = sm + 2 * NMAX + SORTN;

    __shared__ float warp_scan[16];
    __shared__ int   s_kmax;
    __shared__ float s_tau;

    int g   = blockIdx.x;
    int n   = sizes[g];
    int off = g_offsets[g];
    int t   = threadIdx.x;
    int reBase = (N - B) + off;

    for (int i = t; i < n; i += TPB) {
        xs[i] = x[off + i];
        int a = edges[2 * (reBase + i)]     - off;
        int b = edges[2 * (reBase + i) + 1] - off;
        eab[i] = (unsigned)a | ((unsigned)b << 16);
        uc[i] = 0.0f;
        ur[i] = 0.0f;
    }
    if (t == 0) s_kmax = 0;
    float step = 0.5f / (float)g_maxdeg;
    __syncthreads();

    // ---- 20 dual-ascent iterations + final y rebuild ----
    for (int it = 0; it <= NITER; ++it) {
        // y = x - dT(u): chain edges folded analytically
        for (int i = t; i < n; i += TPB) {
            float v = xs[i];
            if (i > 0)     v += uc[i - 1];
            if (i < n - 1) v -= uc[i];
            ys[i] = v;
        }
        __syncthreads();
        // random-edge scatter
        for (int i = t; i < n; i += TPB) {
            unsigned p = eab[i];
            int a = (int)(p & 0xffffu), b = (int)(p >> 16);
            float u = ur[i];
            atomicAdd(&ys[a], -u);
            atomicAdd(&ys[b],  u);
        }
        __syncthreads();
        if (it == NITER) break;
        // u updates (read ys, write uc/ur — disjoint)
        for (int i = t; i < n; i += TPB) {
            if (i < n - 1) {
                float nu = uc[i] + step * (ys[i] - ys[i + 1]);
                uc[i] = fminf(1.0f, fmaxf(-1.0f, nu));
            }
            unsigned p = eab[i];
            int a = (int)(p & 0xffffu), b = (int)(p >> 16);
            float nu = ur[i] + step * (ys[a] - ys[b]);
            ur[i] = fminf(1.0f, fmaxf(-1.0f, nu));
        }
        __syncthreads();
    }

    // ---- sparsemax: z = ys (GAMMA=1) ----
    for (int i = t; i < SORTN; i += TPB)
        S[i] = (i < n) ? ys[i] : -1e30f;
    __syncthreads();

    // bitonic sort, descending
    for (int k = 2; k <= SORTN; k <<= 1) {
        for (int j = k >> 1; j > 0; j >>= 1) {
#pragma unroll
            for (int i = t; i < SORTN; i += TPB) {
                int ix = i ^ j;
                if (ix > i) {
                    float a = S[i], b = S[ix];
                    bool up = ((i & k) == 0);
                    if ((a < b) == up) { S[i] = b; S[ix] = a; }
                }
            }
            __syncthreads();
        }
    }

    // two-level inclusive scan: each thread owns 4 consecutive elements
    float e0 = S[4 * t], e1 = S[4 * t + 1], e2 = S[4 * t + 2], e3 = S[4 * t + 3];
    float r0 = e0, r1 = r0 + e1, r2 = r1 + e2, r3 = r2 + e3;
    float v = r3;
    int lane = t & 31, wid = t >> 5;
#pragma unroll
    for (int d = 1; d < 32; d <<= 1) {
        float o = __shfl_up_sync(0xffffffffu, v, d);
        if (lane >= d) v += o;
    }
    if (lane == 31) warp_scan[wid] = v;
    __syncthreads();
    if (wid == 0 && lane < 16) {
        float w = warp_scan[lane];
#pragma unroll
        for (int d = 1; d < 16; d <<= 1) {
            float o = __shfl_up_sync(0xffffu, w, d);
            if (lane >= d) w += o;
        }
        warp_scan[lane] = w;
    }
    __syncthreads();
    float base = ((wid > 0) ? warp_scan[wid - 1] : 0.0f) + (v - r3);
    CS[4 * t]     = base + r0;
    CS[4 * t + 1] = base + r1;
    CS[4 * t + 2] = base + r2;
    CS[4 * t + 3] = base + r3;
    __syncthreads();

    // support condition: 1 + k*zs_k > cs_k  (k = idx+1), kmax = largest such k
    int kloc = 0;
#pragma unroll
    for (int jj = 0; jj < 4; ++jj) {
        int idx = 4 * t + jj;
        if (idx < n) {
            float kf = (float)(idx + 1);
            if (1.0f + kf * S[idx] > CS[idx]) kloc = idx + 1;
        }
    }
    atomicMax(&s_kmax, kloc);
    __syncthreads();
    if (t == 0) {
        int km = s_kmax;
        s_tau = (CS[km - 1] - 1.0f) / (float)km;
    }
    __syncthreads();
    float tau = s_tau;
    float scale = (float)n;
    for (int i = t; i < n; i += TPB)
        out[off + i] = fmaxf(ys[i] - tau, 0.0f) * scale;
}

// ---------------------------------------------------------------------------
extern "C" void kernel_launch(void* const* d_in, const int* in_sizes, int n_in,
                              void* d_out, int out_size) {
    const float* x     = (const float*)d_in[0];
    const int*   sizes = (const int*)  d_in[1];
    const int*   edges = (const int*)  d_in[2];
    float*       out   = (float*)d_out;
    int N = in_sizes[0];
    int B = in_sizes[1];

    scan_offsets_kernel<<<1, 1024>>>(sizes, B);
    deg_kernel<<<B, 256>>>(sizes, edges, N, B);
    size_t smem = (size_t)(5 * NMAX) * sizeof(float);  // 30720 bytes
    main_kernel<<<B, TPB, smem>>>(x, sizes, edges, out, N, B);
}

// round 2
// speedup vs baseline: 1.5246x; 1.5246x over previous
#include <cuda_runtime.h>

#define NMAX  1536
#define TPB   512
#define EPT   3          // elements per thread (NMAX / TPB)
#define NITER 20

__device__ int g_offsets[2049];
__device__ int g_maxdeg;

// ---------------------------------------------------------------------------
// Kernel 1: exclusive-scan of sizes -> g_offsets, reset g_maxdeg.
// ---------------------------------------------------------------------------
__global__ void scan_offsets_kernel(const int* __restrict__ sizes, int B) {
    __shared__ int warp_sums[32];
    int t = threadIdx.x;
    if (t == 0) g_maxdeg = 0;

    int i0 = 2 * t, i1 = 2 * t + 1;
    int s0 = (i0 < B) ? sizes[i0] : 0;
    int s1 = (i1 < B) ? sizes[i1] : 0;
    int tot = s0 + s1;

    int lane = t & 31, wid = t >> 5;
    int v = tot;
#pragma unroll
    for (int d = 1; d < 32; d <<= 1) {
        int o = __shfl_up_sync(0xffffffffu, v, d);
        if (lane >= d) v += o;
    }
    if (lane == 31) warp_sums[wid] = v;
    __syncthreads();
    if (wid == 0) {
        int w = warp_sums[lane];
#pragma unroll
        for (int d = 1; d < 32; d <<= 1) {
            int o = __shfl_up_sync(0xffffffffu, w, d);
            if (lane >= d) w += o;
        }
        warp_sums[lane] = w;
    }
    __syncthreads();
    int warp_excl = (wid > 0) ? warp_sums[wid - 1] : 0;
    int incl = v + warp_excl;
    int excl = incl - tot;
    if (i0 < B) g_offsets[i0] = excl;
    if (i1 < B) g_offsets[i1] = excl + s0;
    if (i1 == B - 1) g_offsets[B] = incl;
}

// ---------------------------------------------------------------------------
// Kernel 2: per-group degree counts -> global max degree.
// ---------------------------------------------------------------------------
__global__ void deg_kernel(const int* __restrict__ sizes,
                           const int* __restrict__ edges,
                           int N, int B) {
    __shared__ int cnt[NMAX];
    __shared__ int red[8];
    int g = blockIdx.x;
    int n = sizes[g];
    int off = g_offsets[g];
    int t = threadIdx.x;

    for (int i = t; i < n; i += blockDim.x)
        cnt[i] = (n == 1) ? 0 : ((i == 0 || i == n - 1) ? 1 : 2);
    __syncthreads();

    int reBase = (N - B) + off;
    for (int i = t; i < n; i += blockDim.x) {
        int a = edges[2 * (reBase + i)]     - off;
        int b = edges[2 * (reBase + i) + 1] - off;
        atomicAdd(&cnt[a], 1);
        atomicAdd(&cnt[b], 1);
    }
    __syncthreads();

    int m = 0;
    for (int i = t; i < n; i += blockDim.x) m = max(m, cnt[i]);
#pragma unroll
    for (int d = 16; d; d >>= 1) m = max(m, __shfl_xor_sync(0xffffffffu, m, d));
    int lane = t & 31, wid = t >> 5;
    if (lane == 0) red[wid] = m;
    __syncthreads();
    if (t == 0) {
        int nw = (blockDim.x + 31) / 32;
        int mm = red[0];
        for (int w = 1; w < nw; ++w) mm = max(mm, red[w]);
        atomicMax(&g_maxdeg, mm);
    }
}

// ---------------------------------------------------------------------------
// Kernel 3: fused per-group solve (registerized) + Michelot sparsemax.
// Shared: ys[NMAX], uc[NMAX] only (~12.3 KB).
// ---------------------------------------------------------------------------
__global__ void __launch_bounds__(TPB)
main_kernel(const float* __restrict__ x,
            const int*   __restrict__ sizes,
            const int*   __restrict__ edges,
            float*       __restrict__ out,
            int N, int B) {
    __shared__ float ys[NMAX];
    __shared__ float uc[NMAX];
    __shared__ float red_s[16];
    __shared__ int   red_c[16];
    __shared__ float s_tau;
    __shared__ int   s_cnt;

    int g   = blockIdx.x;
    int n   = sizes[g];
    int off = g_offsets[g];
    int t   = threadIdx.x;
    int reBase = (N - B) + off;

    // per-thread registers for owned elements i = t + j*TPB
    float xr[EPT];
    float urr[EPT];
    float ucr[EPT];
    int   ea[EPT], eb[EPT];
    bool  act[EPT];     // i < n
    bool  actc[EPT];    // i < n-1 (has chain edge to i+1)

#pragma unroll
    for (int j = 0; j < EPT; ++j) {
        int i = t + j * TPB;
        act[j]  = (i < n);
        actc[j] = (i < n - 1);
        if (act[j]) {
            xr[j] = x[off + i];
            ea[j] = edges[2 * (reBase + i)]     - off;
            eb[j] = edges[2 * (reBase + i) + 1] - off;
            uc[i] = 0.0f;
        } else {
            xr[j] = 0.0f; ea[j] = 0; eb[j] = 0;
        }
        urr[j] = 0.0f;
        ucr[j] = 0.0f;
    }
    float step = 0.5f / (float)g_maxdeg;
    __syncthreads();

    // ---- 20 dual-ascent iterations (+ final y rebuild on it==NITER) ----
    for (int it = 0; it <= NITER; ++it) {
        // y = x + uc[i-1] - uc[i]  (chain folded; uc[i] from register shadow)
#pragma unroll
        for (int j = 0; j < EPT; ++j) {
            int i = t + j * TPB;
            if (act[j]) {
                float v = xr[j];
                if (i > 0)   v += uc[i - 1];
                if (actc[j]) v -= ucr[j];
                ys[i] = v;
            }
        }
        __syncthreads();
        // random-edge scatter: y[a] -= u, y[b] += u
#pragma unroll
        for (int j = 0; j < EPT; ++j) {
            if (act[j]) {
                float u = urr[j];
                atomicAdd(&ys[ea[j]], -u);
                atomicAdd(&ys[eb[j]],  u);
            }
        }
        __syncthreads();
        if (it == NITER) break;
        // dual updates
#pragma unroll
        for (int j = 0; j < EPT; ++j) {
            int i = t + j * TPB;
            if (act[j]) {
                if (actc[j]) {
                    float nu = ucr[j] + step * (ys[i] - ys[i + 1]);
                    nu = fminf(1.0f, fmaxf(-1.0f, nu));
                    ucr[j] = nu;
                    uc[i] = nu;
                }
                float nu = urr[j] + step * (ys[ea[j]] - ys[eb[j]]);
                urr[j] = fminf(1.0f, fmaxf(-1.0f, nu));
            }
        }
        __syncthreads();
    }

    // ---- sparsemax via Michelot (exact, no sort) ----
    // z = y (GAMMA = 1). Load owned z values to registers.
    float zv[EPT];
#pragma unroll
    for (int j = 0; j < EPT; ++j) {
        int i = t + j * TPB;
        zv[j] = act[j] ? ys[i] : -1e30f;
    }

    int lane = t & 31, wid = t >> 5;

    // initial tau = (sum(z) - 1)/n over full set
    {
        float s = 0.0f;
#pragma unroll
        for (int j = 0; j < EPT; ++j) if (act[j]) s += zv[j];
#pragma unroll
        for (int d = 16; d; d >>= 1) s += __shfl_xor_sync(0xffffffffu, s, d);
        if (lane == 0) red_s[wid] = s;
        __syncthreads();
        if (t == 0) {
            float ss = 0.0f;
#pragma unroll
            for (int w = 0; w < 16; ++w) ss += red_s[w];
            s_tau = (ss - 1.0f) / (float)n;
            s_cnt = n;
        }
        __syncthreads();
    }

    float tau = s_tau;
    int prev_cnt = s_cnt;

    for (int itm = 0; itm < 64; ++itm) {
        float s = 0.0f;
        int   c = 0;
#pragma unroll
        for (int j = 0; j < EPT; ++j) {
            if (act[j] && zv[j] > tau) { s += zv[j]; ++c; }
        }
#pragma unroll
        for (int d = 16; d; d >>= 1) {
            s += __shfl_xor_sync(0xffffffffu, s, d);
            c += __shfl_xor_sync(0xffffffffu, c, d);
        }
        if (lane == 0) { red_s[wid] = s; red_c[wid] = c; }
        __syncthreads();
        if (t == 0) {
            float ss = 0.0f; int cc = 0;
#pragma unroll
            for (int w = 0; w < 16; ++w) { ss += red_s[w]; cc += red_c[w]; }
            s_tau = (ss - 1.0f) / (float)cc;
            s_cnt = cc;
        }
        __syncthreads();
        tau = s_tau;
        int cnt = s_cnt;
        if (cnt == prev_cnt) break;   // active set stable -> converged (exact)
        prev_cnt = cnt;
    }

    float scale = (float)n;
#pragma unroll
    for (int j = 0; j < EPT; ++j) {
        int i = t + j * TPB;
        if (act[j]) out[off + i] = fmaxf(zv[j] - tau, 0.0f) * scale;
    }
}

// ---------------------------------------------------------------------------
extern "C" void kernel_launch(void* const* d_in, const int* in_sizes, int n_in,
                              void* d_out, int out_size) {
    const float* x     = (const float*)d_in[0];
    const int*   sizes = (const int*)  d_in[1];
    const int*   edges = (const int*)  d_in[2];
    float*       out   = (float*)d_out;
    int N = in_sizes[0];
    int B = in_sizes[1];

    scan_offsets_kernel<<<1, 1024>>>(sizes, B);
    deg_kernel<<<B, 256>>>(sizes, edges, N, B);
    main_kernel<<<B, TPB>>>(x, sizes, edges, out, N, B);
}